// round 1
// baseline (speedup 1.0000x reference)
#include <cuda_runtime.h>
#include <cstdint>

// ---------------- problem constants ----------------
#define NB    2
#define LSEQ  2048
#define EDIM  2048
#define HKVN  4
#define DH    128
#define SCH   64      // chunk size S
#define BQ    32      // query blocks L/S
#define GQ    4       // query heads per kv head
#define KTOP  16
#define MCNK  512
#define MROWS 4096    // NB*LSEQ

#define SCALE 0.08838834764831845f   // 1/sqrt(128)

// ---------------- scratch (no cudaMalloc allowed) ----------------
__device__ float g_xnorm[(size_t)MROWS * EDIM];
__device__ float g_q[(size_t)MROWS * EDIM];
__device__ float g_ctx[(size_t)MROWS * EDIM];

// ================= RMSNorm =================
__global__ void rmsnorm_kernel(const float* __restrict__ x,
                               const float* __restrict__ w,
                               float* __restrict__ y)
{
    int row = blockIdx.x;
    int tid = threadIdx.x;
    const float4* xr = (const float4*)(x + (size_t)row * EDIM);
    const float4* wr = (const float4*)w;
    float4 v0 = xr[tid];
    float4 v1 = xr[tid + 256];
    float ss = v0.x*v0.x + v0.y*v0.y + v0.z*v0.z + v0.w*v0.w
             + v1.x*v1.x + v1.y*v1.y + v1.z*v1.z + v1.w*v1.w;
    #pragma unroll
    for (int o = 16; o > 0; o >>= 1) ss += __shfl_xor_sync(0xffffffffu, ss, o);
    __shared__ float red[8];
    if ((tid & 31) == 0) red[tid >> 5] = ss;
    __syncthreads();
    float tot = red[0] + red[1] + red[2] + red[3] + red[4] + red[5] + red[6] + red[7];
    float inv = rsqrtf(tot * (1.0f / (float)EDIM) + 1e-6f);
    float4 w0 = wr[tid], w1 = wr[tid + 256];
    float4 o0, o1;
    o0.x = v0.x * inv * w0.x; o0.y = v0.y * inv * w0.y;
    o0.z = v0.z * inv * w0.z; o0.w = v0.w * inv * w0.w;
    o1.x = v1.x * inv * w1.x; o1.y = v1.y * inv * w1.y;
    o1.z = v1.z * inv * w1.z; o1.w = v1.w * inv * w1.w;
    float4* yr = (float4*)(y + (size_t)row * EDIM);
    yr[tid] = o0;
    yr[tid + 256] = o1;
}

// ================= SGEMM: C[M,2048] = A[M,2048] * B[2048,2048]^T (+Cadd) =================
// BM=BN=128, BK=16, 256 threads, 8x8 microtile. Both operands K-contiguous row-major.
__global__ void __launch_bounds__(256) sgemm_tn_kernel(const float* __restrict__ A,
                                                       const float* __restrict__ B,
                                                       const float* __restrict__ Cadd,
                                                       float* __restrict__ C)
{
    __shared__ float As[16][128];
    __shared__ float Bs[16][128];
    int tid = threadIdx.x;
    int bn = blockIdx.x, bm = blockIdx.y;
    int ty = tid & 15;        // m-octet (16 distinct per warp -> conflict-free a loads)
    int tx = tid >> 4;        // n-octet (2 distinct per warp -> broadcast b loads)
    int lrow = tid >> 2;      // 0..63
    int lc = (tid & 3) << 2;  // 0,4,8,12

    const float* Ab = A + (size_t)(bm * 128) * EDIM;
    const float* Bb = B + (size_t)(bn * 128) * EDIM;

    float acc[8][8];
    #pragma unroll
    for (int i = 0; i < 8; i++)
        #pragma unroll
        for (int j = 0; j < 8; j++) acc[i][j] = 0.0f;

    for (int kt = 0; kt < EDIM; kt += 16) {
        float4 a0 = *(const float4*)(Ab + (size_t)lrow * EDIM + kt + lc);
        float4 a1 = *(const float4*)(Ab + (size_t)(lrow + 64) * EDIM + kt + lc);
        float4 b0 = *(const float4*)(Bb + (size_t)lrow * EDIM + kt + lc);
        float4 b1 = *(const float4*)(Bb + (size_t)(lrow + 64) * EDIM + kt + lc);
        __syncthreads();
        As[lc + 0][lrow] = a0.x; As[lc + 1][lrow] = a0.y;
        As[lc + 2][lrow] = a0.z; As[lc + 3][lrow] = a0.w;
        As[lc + 0][lrow + 64] = a1.x; As[lc + 1][lrow + 64] = a1.y;
        As[lc + 2][lrow + 64] = a1.z; As[lc + 3][lrow + 64] = a1.w;
        Bs[lc + 0][lrow] = b0.x; Bs[lc + 1][lrow] = b0.y;
        Bs[lc + 2][lrow] = b0.z; Bs[lc + 3][lrow] = b0.w;
        Bs[lc + 0][lrow + 64] = b1.x; Bs[lc + 1][lrow + 64] = b1.y;
        Bs[lc + 2][lrow + 64] = b1.z; Bs[lc + 3][lrow + 64] = b1.w;
        __syncthreads();
        #pragma unroll
        for (int k = 0; k < 16; k++) {
            float a[8], b[8];
            *(float4*)&a[0] = *(const float4*)&As[k][ty * 8];
            *(float4*)&a[4] = *(const float4*)&As[k][ty * 8 + 4];
            *(float4*)&b[0] = *(const float4*)&Bs[k][tx * 8];
            *(float4*)&b[4] = *(const float4*)&Bs[k][tx * 8 + 4];
            #pragma unroll
            for (int i = 0; i < 8; i++)
                #pragma unroll
                for (int j = 0; j < 8; j++) acc[i][j] += a[i] * b[j];
        }
    }

    #pragma unroll
    for (int i = 0; i < 8; i++) {
        size_t row = (size_t)(bm * 128 + ty * 8 + i);
        float* crow = C + row * EDIM + bn * 128 + tx * 8;
        if (Cadd) {
            const float* arow = Cadd + row * EDIM + bn * 128 + tx * 8;
            float4 r0 = *(const float4*)(arow);
            float4 r1 = *(const float4*)(arow + 4);
            float4 c0, c1;
            c0.x = acc[i][0] + r0.x; c0.y = acc[i][1] + r0.y;
            c0.z = acc[i][2] + r0.z; c0.w = acc[i][3] + r0.w;
            c1.x = acc[i][4] + r1.x; c1.y = acc[i][5] + r1.y;
            c1.z = acc[i][6] + r1.z; c1.w = acc[i][7] + r1.w;
            *(float4*)(crow) = c0;
            *(float4*)(crow + 4) = c1;
        } else {
            float4 c0, c1;
            c0.x = acc[i][0]; c0.y = acc[i][1]; c0.z = acc[i][2]; c0.w = acc[i][3];
            c1.x = acc[i][4]; c1.y = acc[i][5]; c1.z = acc[i][6]; c1.w = acc[i][7];
            *(float4*)(crow) = c0;
            *(float4*)(crow + 4) = c1;
        }
    }
}

// ================= Attention =================
// One CTA per (n, b, h_kv, g-pair): M = 128 query rows (2 g-heads x 64 s).
// Chunk-pair loop: 2 chunks per iteration -> 8x8 microtiles in both GEMM phases.
// SMEM strides of 129 + interleaved n-mapping give conflict-free hot-loop LDS.
#define QSTR 129
#define SMEM_ATTN (3 * 128 * 129 * 4)

__global__ void __launch_bounds__(256, 1) attn_kernel(const float* __restrict__ q,
                                                      const float* __restrict__ mk,
                                                      const float* __restrict__ mv,
                                                      const int* __restrict__ idxs,
                                                      const float* __restrict__ wts,
                                                      float* __restrict__ ctx)
{
    extern __shared__ float sm[];
    float* Qs  = sm;                  // [128][129]
    float* KVs = sm + 128 * QSTR;     // [128][129] (K pair, then reused for V pair)
    float* Ps  = sm + 2 * 128 * QSTR; // [128][129] scores -> probabilities

    __shared__ int   s_idx[KTOP];
    __shared__ float s_w[KTOP];

    int tid = threadIdx.x;
    int bid = blockIdx.x;
    int gp = bid & 1;
    int h  = (bid >> 1) & 3;
    int b  = (bid >> 3) & 31;
    int n  = bid >> 8;

    int row0 = n * LSEQ + b * SCH;           // global q/ctx row base
    int col0 = h * (GQ * DH) + gp * 256;     // global column base for this g-pair

    if (tid < KTOP) {
        int off = ((n * BQ + b) * HKVN + h) * KTOP + tid;
        s_idx[tid] = idxs[off];
        s_w[tid]   = wts[off];
    }

    // ---- load Q tile [128][128] into SMEM (natural, stride 129) ----
    #pragma unroll
    for (int it = 0; it < 16; ++it) {
        int u = tid + it * 256;
        int m = u >> 5;
        int d4 = (u & 31) << 2;
        int s_ = m & 63;
        int gi = m >> 6;
        float4 v = *(const float4*)(q + (size_t)(row0 + s_) * EDIM + col0 + gi * DH + d4);
        float* dst = Qs + m * QSTR + d4;
        dst[0] = v.x; dst[1] = v.y; dst[2] = v.z; dst[3] = v.w;
    }

    int tn16 = tid & 15;
    int tmq  = tid >> 4;
    int mbase = tmq * 8;
    int warp = tid >> 5;
    int lane = tid & 31;

    float acc[8][8];
    #pragma unroll
    for (int i = 0; i < 8; i++)
        #pragma unroll
        for (int u = 0; u < 8; u++) acc[i][u] = 0.0f;

    __syncthreads();

    for (int cp = 0; cp < 8; ++cp) {
        // ---- load K chunk pair (chunks 2cp, 2cp+1) into KVs ----
        #pragma unroll
        for (int it = 0; it < 16; ++it) {
            int u = tid + it * 256;
            int nr = u >> 5;
            int d4 = (u & 31) << 2;
            int c = 2 * cp + (nr >> 6);
            int j = nr & 63;
            int ci = s_idx[c];
            size_t base = ((size_t)(n * (MCNK * SCH) + ci * SCH + j) * HKVN + h) * DH;
            float4 v = *(const float4*)(mk + base + d4);
            float* dst = KVs + nr * QSTR + d4;
            dst[0] = v.x; dst[1] = v.y; dst[2] = v.z; dst[3] = v.w;
        }
        __syncthreads();

        // ---- scores: S[m][nk] = sum_d Q[m][d] * K[nk][d], m in 8 rows, nk = tn16+16u ----
        float sc[8][8];
        #pragma unroll
        for (int i = 0; i < 8; i++)
            #pragma unroll
            for (int u = 0; u < 8; u++) sc[i][u] = 0.0f;

        #pragma unroll 4
        for (int d = 0; d < 128; ++d) {
            float a[8], bb[8];
            #pragma unroll
            for (int i = 0; i < 8; i++) a[i] = Qs[(mbase + i) * QSTR + d];
            #pragma unroll
            for (int u = 0; u < 8; u++) bb[u] = KVs[(tn16 + 16 * u) * QSTR + d];
            #pragma unroll
            for (int i = 0; i < 8; i++)
                #pragma unroll
                for (int u = 0; u < 8; u++) sc[i][u] += a[i] * bb[u];
        }
        #pragma unroll
        for (int i = 0; i < 8; i++)
            #pragma unroll
            for (int u = 0; u < 8; u++)
                Ps[(mbase + i) * QSTR + tn16 + 16 * u] = sc[i][u] * SCALE;
        __syncthreads();   // K reads done, S writes done

        // ---- load V chunk pair into KVs (overwrites K) ----
        #pragma unroll
        for (int it = 0; it < 16; ++it) {
            int u = tid + it * 256;
            int nr = u >> 5;
            int d4 = (u & 31) << 2;
            int c = 2 * cp + (nr >> 6);
            int j = nr & 63;
            int ci = s_idx[c];
            size_t base = ((size_t)(n * (MCNK * SCH) + ci * SCH + j) * HKVN + h) * DH;
            float4 v = *(const float4*)(mv + base + d4);
            float* dst = KVs + nr * QSTR + d4;
            dst[0] = v.x; dst[1] = v.y; dst[2] = v.z; dst[3] = v.w;
        }

        // ---- softmax1 per row, per 64-wide chunk segment; fold chunk weight ----
        {
            float w0 = s_w[2 * cp];
            float w1 = s_w[2 * cp + 1];
            #pragma unroll 2
            for (int rr = 0; rr < 16; ++rr) {
                int r = warp * 16 + rr;
                float* prow = Ps + r * QSTR;
                float v0 = prow[lane];
                float v1 = prow[lane + 32];
                float v2 = prow[lane + 64];
                float v3 = prow[lane + 96];
                float m0 = fmaxf(v0, v1);
                float m1 = fmaxf(v2, v3);
                #pragma unroll
                for (int o = 16; o > 0; o >>= 1) {
                    m0 = fmaxf(m0, __shfl_xor_sync(0xffffffffu, m0, o));
                    m1 = fmaxf(m1, __shfl_xor_sync(0xffffffffu, m1, o));
                }
                m0 = fmaxf(m0, 0.0f);
                m1 = fmaxf(m1, 0.0f);
                float e0 = __expf(v0 - m0), e1 = __expf(v1 - m0);
                float e2 = __expf(v2 - m1), e3 = __expf(v3 - m1);
                float s0 = e0 + e1, s1 = e2 + e3;
                #pragma unroll
                for (int o = 16; o > 0; o >>= 1) {
                    s0 += __shfl_xor_sync(0xffffffffu, s0, o);
                    s1 += __shfl_xor_sync(0xffffffffu, s1, o);
                }
                float r0 = w0 / (s0 + __expf(-m0));
                float r1 = w1 / (s1 + __expf(-m1));
                prow[lane]      = e0 * r0;
                prow[lane + 32] = e1 * r0;
                prow[lane + 64] = e2 * r1;
                prow[lane + 96] = e3 * r1;
            }
        }
        __syncthreads();   // V loaded, P normalized

        // ---- PV: ctx[m][d] += sum_j P[m][j] * V[j][d], d = tn16+16u ----
        #pragma unroll 4
        for (int j = 0; j < 128; ++j) {
            float a[8], bb[8];
            #pragma unroll
            for (int i = 0; i < 8; i++) a[i] = Ps[(mbase + i) * QSTR + j];
            #pragma unroll
            for (int u = 0; u < 8; u++) bb[u] = KVs[j * QSTR + tn16 + 16 * u];
            #pragma unroll
            for (int i = 0; i < 8; i++)
                #pragma unroll
                for (int u = 0; u < 8; u++) acc[i][u] += a[i] * bb[u];
        }
        __syncthreads();   // PV reads done; KVs/Ps reusable next iteration
    }

    // ---- write ctx ----
    #pragma unroll
    for (int i = 0; i < 8; i++) {
        int m = mbase + i;
        int s_ = m & 63;
        int gi = m >> 6;
        float* crow = ctx + (size_t)(row0 + s_) * EDIM + col0 + gi * DH;
        #pragma unroll
        for (int u = 0; u < 8; u++) crow[tn16 + 16 * u] = acc[i][u];
    }
}

// ================= launch =================
extern "C" void kernel_launch(void* const* d_in, const int* in_sizes, int n_in,
                              void* d_out, int out_size)
{
    const float* hidden = (const float*)d_in[0];
    const float* wts    = (const float*)d_in[1];
    const float* mk     = (const float*)d_in[2];
    const float* mv     = (const float*)d_in[3];
    const int*   idx    = (const int*)d_in[4];
    const float* pw     = (const float*)d_in[5];
    const float* qw     = (const float*)d_in[6];
    const float* ow     = (const float*)d_in[7];
    float* out = (float*)d_out;

    float *xn, *qbuf, *ctxp;
    cudaGetSymbolAddress((void**)&xn, g_xnorm);
    cudaGetSymbolAddress((void**)&qbuf, g_q);
    cudaGetSymbolAddress((void**)&ctxp, g_ctx);

    cudaFuncSetAttribute(attn_kernel, cudaFuncAttributeMaxDynamicSharedMemorySize, SMEM_ATTN);

    rmsnorm_kernel<<<MROWS, 256>>>(hidden, pw, xn);
    sgemm_tn_kernel<<<dim3(16, 32), 256>>>(xn, qw, nullptr, qbuf);
    attn_kernel<<<NB * BQ * HKVN * 2, 256, SMEM_ATTN>>>(qbuf, mk, mv, idx, wts, ctxp);
    sgemm_tn_kernel<<<dim3(16, 32), 256>>>(ctxp, ow, hidden, out);
}

// round 3
// speedup vs baseline: 2.2669x; 2.2669x over previous
#include <cuda_runtime.h>
#include <cuda_bf16.h>
#include <cstdint>

// ---------------- problem constants ----------------
#define NB    2
#define LSEQ  2048
#define EDIM  2048
#define HKVN  4
#define DH    128
#define SCH   64
#define BQ    32
#define GQ    4
#define KTOP  16
#define MCNK  512
#define MROWS 4096

#define SCALE 0.08838834764831845f

// ---------------- scratch ----------------
__device__ __nv_bfloat16 g_xn_h[(size_t)MROWS * EDIM];
__device__ __nv_bfloat16 g_xn_l[(size_t)MROWS * EDIM];
__device__ __nv_bfloat16 g_qw_h[(size_t)EDIM * EDIM];
__device__ __nv_bfloat16 g_qw_l[(size_t)EDIM * EDIM];
__device__ __nv_bfloat16 g_ow_h[(size_t)EDIM * EDIM];
__device__ __nv_bfloat16 g_ow_l[(size_t)EDIM * EDIM];
__device__ __nv_bfloat16 g_cx_h[(size_t)MROWS * EDIM];
__device__ __nv_bfloat16 g_cx_l[(size_t)MROWS * EDIM];
__device__ float g_q[(size_t)MROWS * EDIM];
__device__ float g_ctx[(size_t)MROWS * EDIM];

// ---------------- helpers ----------------
__device__ __forceinline__ void split_write(float v, __nv_bfloat16* h, __nv_bfloat16* l, size_t i) {
    __nv_bfloat16 hi = __float2bfloat16(v);
    h[i] = hi;
    l[i] = __float2bfloat16(v - __bfloat162float(hi));
}

__device__ __forceinline__ void cp16(uint32_t dst, const void* src) {
    asm volatile("cp.async.cg.shared.global [%0], [%1], 16;\n" :: "r"(dst), "l"(src));
}
__device__ __forceinline__ void ldm_x4(uint32_t* r, uint32_t a) {
    asm volatile("ldmatrix.sync.aligned.m8n8.x4.shared.b16 {%0,%1,%2,%3}, [%4];\n"
                 : "=r"(r[0]), "=r"(r[1]), "=r"(r[2]), "=r"(r[3]) : "r"(a));
}
__device__ __forceinline__ void ldm_x4t(uint32_t* r, uint32_t a) {
    asm volatile("ldmatrix.sync.aligned.m8n8.x4.trans.shared.b16 {%0,%1,%2,%3}, [%4];\n"
                 : "=r"(r[0]), "=r"(r[1]), "=r"(r[2]), "=r"(r[3]) : "r"(a));
}
__device__ __forceinline__ void mma_bf16(float* d, const uint32_t* a, uint32_t b0, uint32_t b1) {
    asm volatile("mma.sync.aligned.m16n8k16.row.col.f32.bf16.bf16.f32 "
                 "{%0,%1,%2,%3}, {%4,%5,%6,%7}, {%8,%9}, {%0,%1,%2,%3};\n"
                 : "+f"(d[0]), "+f"(d[1]), "+f"(d[2]), "+f"(d[3])
                 : "r"(a[0]), "r"(a[1]), "r"(a[2]), "r"(a[3]), "r"(b0), "r"(b1));
}

// ================= RMSNorm + split =================
__global__ void rmsnorm_split_kernel(const float* __restrict__ x,
                                     const float* __restrict__ w,
                                     __nv_bfloat16* __restrict__ yh,
                                     __nv_bfloat16* __restrict__ yl)
{
    int row = blockIdx.x;
    int tid = threadIdx.x;
    const float4* xr = (const float4*)(x + (size_t)row * EDIM);
    const float4* wr = (const float4*)w;
    float4 v0 = xr[tid];
    float4 v1 = xr[tid + 256];
    float ss = v0.x*v0.x + v0.y*v0.y + v0.z*v0.z + v0.w*v0.w
             + v1.x*v1.x + v1.y*v1.y + v1.z*v1.z + v1.w*v1.w;
    #pragma unroll
    for (int o = 16; o > 0; o >>= 1) ss += __shfl_xor_sync(0xffffffffu, ss, o);
    __shared__ float red[8];
    if ((tid & 31) == 0) red[tid >> 5] = ss;
    __syncthreads();
    float tot = red[0] + red[1] + red[2] + red[3] + red[4] + red[5] + red[6] + red[7];
    float inv = rsqrtf(tot * (1.0f / (float)EDIM) + 1e-6f);
    float4 w0 = wr[tid], w1 = wr[tid + 256];
    float o0[4] = { v0.x*inv*w0.x, v0.y*inv*w0.y, v0.z*inv*w0.z, v0.w*inv*w0.w };
    float o1[4] = { v1.x*inv*w1.x, v1.y*inv*w1.y, v1.z*inv*w1.z, v1.w*inv*w1.w };
    size_t base = (size_t)row * EDIM;
    #pragma unroll
    for (int j = 0; j < 4; j++) split_write(o0[j], yh, yl, base + tid*4 + j);
    #pragma unroll
    for (int j = 0; j < 4; j++) split_write(o1[j], yh, yl, base + (tid + 256)*4 + j);
}

// ================= elementwise split =================
__global__ void split_kernel(const float* __restrict__ in,
                             __nv_bfloat16* __restrict__ h,
                             __nv_bfloat16* __restrict__ l,
                             int n4)
{
    int i = blockIdx.x * blockDim.x + threadIdx.x;
    if (i >= n4) return;
    float4 v = ((const float4*)in)[i];
    size_t b = (size_t)i * 4;
    split_write(v.x, h, l, b + 0);
    split_write(v.y, h, l, b + 1);
    split_write(v.z, h, l, b + 2);
    split_write(v.w, h, l, b + 3);
}

// ================= bf16-split tensor-core GEMM =================
#define ASTR_B 80
#define PLANE_B 10240
#define BOFF_B 20480
#define STAGE_B 40960
#define GEMM_SMEM (2 * STAGE_B)

__global__ void __launch_bounds__(256) gemm3_kernel(
    const __nv_bfloat16* __restrict__ Ah, const __nv_bfloat16* __restrict__ Al,
    const __nv_bfloat16* __restrict__ Bh, const __nv_bfloat16* __restrict__ Bl,
    const float* __restrict__ Cadd, float* __restrict__ C)
{
    extern __shared__ char smem[];
    uint32_t sbase = (uint32_t)__cvta_generic_to_shared(smem);
    int tid = threadIdx.x;
    int bn = blockIdx.x, bm = blockIdx.y;
    int lane = tid & 31;
    int wid = tid >> 5;
    int wm = wid & 1;
    int wn = wid >> 1;

    size_t rowA0 = (size_t)bm * 128;
    size_t rowB0 = (size_t)bn * 128;

    auto load_stage = [&](int kt, int s) {
        uint32_t d0 = sbase + s * STAGE_B;
        #pragma unroll
        for (int ii = 0; ii < 4; ii++) {
            int i = tid + ii * 256;
            int plane = i >> 9, rr = (i >> 2) & 127, c4 = i & 3;
            const __nv_bfloat16* src = (plane ? Al : Ah) + (rowA0 + rr) * EDIM + kt + c4 * 8;
            cp16(d0 + plane * PLANE_B + rr * ASTR_B + c4 * 16, src);
        }
        #pragma unroll
        for (int ii = 0; ii < 4; ii++) {
            int i = tid + ii * 256;
            int plane = i >> 9, rr = (i >> 2) & 127, c4 = i & 3;
            const __nv_bfloat16* src = (plane ? Bl : Bh) + (rowB0 + rr) * EDIM + kt + c4 * 8;
            cp16(d0 + BOFF_B + plane * PLANE_B + rr * ASTR_B + c4 * 16, src);
        }
        asm volatile("cp.async.commit_group;\n" ::);
    };

    float acc[4][4][4];
    #pragma unroll
    for (int mi = 0; mi < 4; mi++)
        #pragma unroll
        for (int ni = 0; ni < 4; ni++)
            #pragma unroll
            for (int r = 0; r < 4; r++) acc[mi][ni][r] = 0.0f;

    uint32_t fl = (uint32_t)((lane & 15) * ASTR_B + (lane >> 4) * 16);
    uint32_t aw = (uint32_t)(wm * 64) * ASTR_B;
    uint32_t bw = (uint32_t)(wn * 32) * ASTR_B;

    load_stage(0, 0);

    const int NIT = EDIM / 32;
    for (int it = 0; it < NIT; it++) {
        if (it + 1 < NIT) {
            load_stage((it + 1) * 32, (it + 1) & 1);
            asm volatile("cp.async.wait_group 1;\n" ::);
        } else {
            asm volatile("cp.async.wait_group 0;\n" ::);
        }
        __syncthreads();

        uint32_t sb = sbase + (it & 1) * STAGE_B;
        #pragma unroll
        for (int ks = 0; ks < 2; ks++) {
            uint32_t bh[2][4], bl[2][4];
            #pragma unroll
            for (int np = 0; np < 2; np++) {
                uint32_t b0 = sb + BOFF_B + bw + (uint32_t)(np * 16) * ASTR_B + ks * 32 + fl;
                ldm_x4(bh[np], b0);
                ldm_x4(bl[np], b0 + PLANE_B);
            }
            #pragma unroll
            for (int mi = 0; mi < 4; mi++) {
                uint32_t ah[4], al[4];
                uint32_t a0 = sb + aw + (uint32_t)(mi * 16) * ASTR_B + ks * 32 + fl;
                ldm_x4(ah, a0);
                ldm_x4(al, a0 + PLANE_B);
                #pragma unroll
                for (int ni = 0; ni < 4; ni++) {
                    int np = ni >> 1, sel = ni & 1;
                    uint32_t bh0 = bh[np][sel], bh1 = bh[np][sel + 2];
                    uint32_t bl0 = bl[np][sel], bl1 = bl[np][sel + 2];
                    mma_bf16(acc[mi][ni], ah, bh0, bh1);
                    mma_bf16(acc[mi][ni], ah, bl0, bl1);
                    mma_bf16(acc[mi][ni], al, bh0, bh1);
                }
            }
        }
        __syncthreads();
    }

    int r0 = bm * 128 + wm * 64 + (lane >> 2);
    int c0 = bn * 128 + wn * 32 + (lane & 3) * 2;
    #pragma unroll
    for (int mi = 0; mi < 4; mi++)
        #pragma unroll
        for (int ni = 0; ni < 4; ni++) {
            int rr = r0 + mi * 16;
            int cc = c0 + ni * 8;
            float2 v0 = { acc[mi][ni][0], acc[mi][ni][1] };
            float2 v1 = { acc[mi][ni][2], acc[mi][ni][3] };
            if (Cadd) {
                float2 a0 = *(const float2*)(Cadd + (size_t)rr * EDIM + cc);
                float2 a1 = *(const float2*)(Cadd + (size_t)(rr + 8) * EDIM + cc);
                v0.x += a0.x; v0.y += a0.y;
                v1.x += a1.x; v1.y += a1.y;
            }
            *(float2*)(C + (size_t)rr * EDIM + cc) = v0;
            *(float2*)(C + (size_t)(rr + 8) * EDIM + cc) = v1;
        }
}

// ================= Attention (tensor-core, split-bf16) =================
#define KSTR  136                  // halves per smem row
#define KSTRB 272                  // bytes per smem row
#define PLB   (128 * KSTRB)        // one plane = 34816 B
#define REG_Q  0
#define REG_KV (2 * PLB)
#define REG_P  (4 * PLB)
#define ATTN_SMEM (6 * PLB)        // 208896 B

__global__ void __launch_bounds__(256, 1) attn_mma_kernel(
    const float* __restrict__ q,
    const float* __restrict__ mk,
    const float* __restrict__ mv,
    const int* __restrict__ idxs,
    const float* __restrict__ wts,
    float* __restrict__ ctx)
{
    extern __shared__ char sm[];
    uint32_t sb = (uint32_t)__cvta_generic_to_shared(sm);

    __shared__ int   s_idx[KTOP];
    __shared__ float s_w[KTOP];
    __shared__ float s_mx[128][4];
    __shared__ float s_sm[128][4];

    int tid = threadIdx.x;
    int lane = tid & 31;
    int wid = tid >> 5;
    int wm = wid & 1;      // m half (64 rows)
    int wn = wid >> 1;     // n slice (32 cols of 128)

    int bid = blockIdx.x;
    int gp = bid & 1;
    int h  = (bid >> 1) & 3;
    int b  = (bid >> 3) & 31;
    int n  = bid >> 8;

    int row0 = n * LSEQ + b * SCH;
    int col0 = h * (GQ * DH) + gp * 256;

    if (tid < KTOP) {
        int off = ((n * BQ + b) * HKVN + h) * KTOP + tid;
        s_idx[tid] = idxs[off];
        s_w[tid]   = wts[off];
    }

    // ---- Q load + split to planes ----
    #pragma unroll
    for (int it = 0; it < 16; ++it) {
        int u = tid + it * 256;
        int m = u >> 5;
        int d4 = (u & 31) << 2;
        int s_ = m & 63;
        int gi = m >> 6;
        float4 v = *(const float4*)(q + (size_t)(row0 + s_) * EDIM + col0 + gi * DH + d4);
        char* hb = sm + REG_Q + m * KSTRB + d4 * 2;
        __nv_bfloat16 hx = __float2bfloat16(v.x), hy = __float2bfloat16(v.y);
        __nv_bfloat16 hz = __float2bfloat16(v.z), hw = __float2bfloat16(v.w);
        ((__nv_bfloat162*)hb)[0] = __nv_bfloat162(hx, hy);
        ((__nv_bfloat162*)hb)[1] = __nv_bfloat162(hz, hw);
        char* lb = hb + PLB;
        ((__nv_bfloat162*)lb)[0] = __nv_bfloat162(
            __float2bfloat16(v.x - __bfloat162float(hx)), __float2bfloat16(v.y - __bfloat162float(hy)));
        ((__nv_bfloat162*)lb)[1] = __nv_bfloat162(
            __float2bfloat16(v.z - __bfloat162float(hz)), __float2bfloat16(v.w - __bfloat162float(hw)));
    }

    float cacc[4][4][4];
    #pragma unroll
    for (int mi = 0; mi < 4; mi++)
        #pragma unroll
        for (int ni = 0; ni < 4; ni++)
            #pragma unroll
            for (int r = 0; r < 4; r++) cacc[mi][ni][r] = 0.0f;

    uint32_t fl = (uint32_t)((lane & 15) * KSTRB + (lane >> 4) * 16);
    uint32_t qa = sb + REG_Q + (uint32_t)(wm * 64) * KSTRB + fl;
    uint32_t pa = sb + REG_P + (uint32_t)(wm * 64) * KSTRB + fl;
    uint32_t kb = sb + REG_KV + (uint32_t)(wn * 32) * KSTRB + fl;

    __syncthreads();

    for (int cp = 0; cp < 8; ++cp) {
        // ---- K pair load + split ----
        #pragma unroll
        for (int it = 0; it < 16; ++it) {
            int u = tid + it * 256;
            int nr = u >> 5;
            int d4 = (u & 31) << 2;
            int c = 2 * cp + (nr >> 6);
            int j = nr & 63;
            int ci = s_idx[c];
            size_t base = ((size_t)(n * (MCNK * SCH) + ci * SCH + j) * HKVN + h) * DH;
            float4 v = *(const float4*)(mk + base + d4);
            char* hb = sm + REG_KV + nr * KSTRB + d4 * 2;
            __nv_bfloat16 hx = __float2bfloat16(v.x), hy = __float2bfloat16(v.y);
            __nv_bfloat16 hz = __float2bfloat16(v.z), hw = __float2bfloat16(v.w);
            ((__nv_bfloat162*)hb)[0] = __nv_bfloat162(hx, hy);
            ((__nv_bfloat162*)hb)[1] = __nv_bfloat162(hz, hw);
            char* lb = hb + PLB;
            ((__nv_bfloat162*)lb)[0] = __nv_bfloat162(
                __float2bfloat16(v.x - __bfloat162float(hx)), __float2bfloat16(v.y - __bfloat162float(hy)));
            ((__nv_bfloat162*)lb)[1] = __nv_bfloat162(
                __float2bfloat16(v.z - __bfloat162float(hz)), __float2bfloat16(v.w - __bfloat162float(hw)));
        }
        __syncthreads();

        // ---- QK^T (3-pass split) ----
        float sacc[4][4][4];
        #pragma unroll
        for (int mi = 0; mi < 4; mi++)
            #pragma unroll
            for (int ni = 0; ni < 4; ni++)
                #pragma unroll
                for (int r = 0; r < 4; r++) sacc[mi][ni][r] = 0.0f;

        #pragma unroll
        for (int ks = 0; ks < 8; ks++) {
            uint32_t bh[2][4], bl[2][4];
            #pragma unroll
            for (int np = 0; np < 2; np++) {
                uint32_t b0 = kb + (uint32_t)(np * 16) * KSTRB + ks * 32;
                ldm_x4(bh[np], b0);
                ldm_x4(bl[np], b0 + PLB);
            }
            #pragma unroll
            for (int mi = 0; mi < 4; mi++) {
                uint32_t ah[4], al[4];
                uint32_t a0 = qa + (uint32_t)(mi * 16) * KSTRB + ks * 32;
                ldm_x4(ah, a0);
                ldm_x4(al, a0 + PLB);
                #pragma unroll
                for (int ni = 0; ni < 4; ni++) {
                    int np = ni >> 1, sel = ni & 1;
                    uint32_t b0h = bh[np][sel], b1h = bh[np][sel + 2];
                    uint32_t b0l = bl[np][sel], b1l = bl[np][sel + 2];
                    mma_bf16(sacc[mi][ni], ah, b0h, b1h);
                    mma_bf16(sacc[mi][ni], ah, b0l, b1l);
                    mma_bf16(sacc[mi][ni], al, b0h, b1h);
                }
            }
        }

        // ---- softmax1 on register scores ----
        int rt = wm * 64 + (lane >> 2);
        // pass 1: per-warp row max
        #pragma unroll
        for (int mi = 0; mi < 4; mi++) {
            float mt = -1e30f, mb = -1e30f;
            #pragma unroll
            for (int ni = 0; ni < 4; ni++) {
                mt = fmaxf(mt, fmaxf(sacc[mi][ni][0], sacc[mi][ni][1]));
                mb = fmaxf(mb, fmaxf(sacc[mi][ni][2], sacc[mi][ni][3]));
            }
            mt = fmaxf(mt, __shfl_xor_sync(0xffffffffu, mt, 1));
            mt = fmaxf(mt, __shfl_xor_sync(0xffffffffu, mt, 2));
            mb = fmaxf(mb, __shfl_xor_sync(0xffffffffu, mb, 1));
            mb = fmaxf(mb, __shfl_xor_sync(0xffffffffu, mb, 2));
            if ((lane & 3) == 0) {
                s_mx[rt + mi * 16][wn] = mt;
                s_mx[rt + mi * 16 + 8][wn] = mb;
            }
        }
        __syncthreads();
        // pass 2: exp + per-warp row sum (overwrite sacc with e)
        #pragma unroll
        for (int mi = 0; mi < 4; mi++) {
            int r1 = rt + mi * 16, r2 = r1 + 8;
            float mt = fmaxf(fmaxf(s_mx[r1][wn], s_mx[r1][wn ^ 1]), 0.0f);
            float mb = fmaxf(fmaxf(s_mx[r2][wn], s_mx[r2][wn ^ 1]), 0.0f);
            float st = 0.0f, sbt = 0.0f;
            #pragma unroll
            for (int ni = 0; ni < 4; ni++) {
                float e0 = __expf(sacc[mi][ni][0] * SCALE - mt);
                float e1 = __expf(sacc[mi][ni][1] * SCALE - mt);
                float e2 = __expf(sacc[mi][ni][2] * SCALE - mb);
                float e3 = __expf(sacc[mi][ni][3] * SCALE - mb);
                sacc[mi][ni][0] = e0; sacc[mi][ni][1] = e1;
                sacc[mi][ni][2] = e2; sacc[mi][ni][3] = e3;
                st += e0 + e1; sbt += e2 + e3;
            }
            st += __shfl_xor_sync(0xffffffffu, st, 1);
            st += __shfl_xor_sync(0xffffffffu, st, 2);
            sbt += __shfl_xor_sync(0xffffffffu, sbt, 1);
            sbt += __shfl_xor_sync(0xffffffffu, sbt, 2);
            if ((lane & 3) == 0) {
                s_sm[r1][wn] = st;
                s_sm[r2][wn] = sbt;
            }
        }
        __syncthreads();
        // pass 3: normalize, fold weight, split-write P planes
        float wgt = s_w[2 * cp + (wn >> 1)];
        #pragma unroll
        for (int mi = 0; mi < 4; mi++) {
            int r1 = rt + mi * 16, r2 = r1 + 8;
            float mt = fmaxf(fmaxf(s_mx[r1][wn], s_mx[r1][wn ^ 1]), 0.0f);
            float mb = fmaxf(fmaxf(s_mx[r2][wn], s_mx[r2][wn ^ 1]), 0.0f);
            float sc1 = wgt / (s_sm[r1][wn] + s_sm[r1][wn ^ 1] + __expf(-mt));
            float sc2 = wgt / (s_sm[r2][wn] + s_sm[r2][wn ^ 1] + __expf(-mb));
            #pragma unroll
            for (int ni = 0; ni < 4; ni++) {
                float p0 = sacc[mi][ni][0] * sc1, p1 = sacc[mi][ni][1] * sc1;
                float p2 = sacc[mi][ni][2] * sc2, p3 = sacc[mi][ni][3] * sc2;
                int cbyte = (wn * 32 + ni * 8 + (lane & 3) * 2) * 2;
                char* hb1 = sm + REG_P + r1 * KSTRB + cbyte;
                char* hb2 = sm + REG_P + r2 * KSTRB + cbyte;
                __nv_bfloat16 h0 = __float2bfloat16(p0), h1 = __float2bfloat16(p1);
                __nv_bfloat16 h2 = __float2bfloat16(p2), h3 = __float2bfloat16(p3);
                *(__nv_bfloat162*)hb1 = __nv_bfloat162(h0, h1);
                *(__nv_bfloat162*)hb2 = __nv_bfloat162(h2, h3);
                *(__nv_bfloat162*)(hb1 + PLB) = __nv_bfloat162(
                    __float2bfloat16(p0 - __bfloat162float(h0)), __float2bfloat16(p1 - __bfloat162float(h1)));
                *(__nv_bfloat162*)(hb2 + PLB) = __nv_bfloat162(
                    __float2bfloat16(p2 - __bfloat162float(h2)), __float2bfloat16(p3 - __bfloat162float(h3)));
            }
        }
        __syncthreads();

        // ---- V pair load + split (overwrites K planes) ----
        #pragma unroll
        for (int it = 0; it < 16; ++it) {
            int u = tid + it * 256;
            int nr = u >> 5;
            int d4 = (u & 31) << 2;
            int c = 2 * cp + (nr >> 6);
            int j = nr & 63;
            int ci = s_idx[c];
            size_t base = ((size_t)(n * (MCNK * SCH) + ci * SCH + j) * HKVN + h) * DH;
            float4 v = *(const float4*)(mv + base + d4);
            char* hb = sm + REG_KV + nr * KSTRB + d4 * 2;
            __nv_bfloat16 hx = __float2bfloat16(v.x), hy = __float2bfloat16(v.y);
            __nv_bfloat16 hz = __float2bfloat16(v.z), hw = __float2bfloat16(v.w);
            ((__nv_bfloat162*)hb)[0] = __nv_bfloat162(hx, hy);
            ((__nv_bfloat162*)hb)[1] = __nv_bfloat162(hz, hw);
            char* lb = hb + PLB;
            ((__nv_bfloat162*)lb)[0] = __nv_bfloat162(
                __float2bfloat16(v.x - __bfloat162float(hx)), __float2bfloat16(v.y - __bfloat162float(hy)));
            ((__nv_bfloat162*)lb)[1] = __nv_bfloat162(
                __float2bfloat16(v.z - __bfloat162float(hz)), __float2bfloat16(v.w - __bfloat162float(hw)));
        }
        __syncthreads();

        // ---- PV: ctx += P * V ----
        #pragma unroll
        for (int ks = 0; ks < 8; ks++) {
            // B via ldmatrix.trans on V[j][d]: rows = j (k dim), col bytes = d
            uint32_t vh[2][4], vl[2][4];
            #pragma unroll
            for (int np = 0; np < 2; np++) {
                uint32_t b0 = sb + REG_KV + (uint32_t)(ks * 16) * KSTRB + wn * 64 + np * 32 + fl;
                ldm_x4t(vh[np], b0);
                ldm_x4t(vl[np], b0 + PLB);
            }
            #pragma unroll
            for (int mi = 0; mi < 4; mi++) {
                uint32_t ph[4], pl[4];
                uint32_t a0 = pa + (uint32_t)(mi * 16) * KSTRB + ks * 32;
                ldm_x4(ph, a0);
                ldm_x4(pl, a0 + PLB);
                #pragma unroll
                for (int ni = 0; ni < 4; ni++) {
                    int np = ni >> 1, sel = ni & 1;
                    uint32_t b0h = vh[np][sel * 2], b1h = vh[np][sel * 2 + 1];
                    uint32_t b0l = vl[np][sel * 2], b1l = vl[np][sel * 2 + 1];
                    mma_bf16(cacc[mi][ni], ph, b0h, b1h);
                    mma_bf16(cacc[mi][ni], ph, b0l, b1l);
                    mma_bf16(cacc[mi][ni], pl, b0h, b1h);
                }
            }
        }
        __syncthreads();
    }

    // ---- epilogue: ctx fp32 out ----
    #pragma unroll
    for (int mi = 0; mi < 4; mi++) {
        #pragma unroll
        for (int ni = 0; ni < 4; ni++) {
            int r1 = wm * 64 + mi * 16 + (lane >> 2);
            int cc = wn * 32 + ni * 8 + (lane & 3) * 2;
            #pragma unroll
            for (int half = 0; half < 2; half++) {
                int m = r1 + half * 8;
                int s_ = m & 63;
                int gi = m >> 6;
                float2 v = { cacc[mi][ni][half * 2], cacc[mi][ni][half * 2 + 1] };
                *(float2*)(ctx + (size_t)(row0 + s_) * EDIM + col0 + gi * DH + cc) = v;
            }
        }
    }
}

// ================= launch =================
extern "C" void kernel_launch(void* const* d_in, const int* in_sizes, int n_in,
                              void* d_out, int out_size)
{
    const float* hidden = (const float*)d_in[0];
    const float* wts    = (const float*)d_in[1];
    const float* mk     = (const float*)d_in[2];
    const float* mv     = (const float*)d_in[3];
    const int*   idx    = (const int*)d_in[4];
    const float* pw     = (const float*)d_in[5];
    const float* qw     = (const float*)d_in[6];
    const float* ow     = (const float*)d_in[7];
    float* out = (float*)d_out;

    __nv_bfloat16 *xnh, *xnl, *qwh, *qwl, *owh, *owl, *cxh, *cxl;
    float *qbuf, *ctxp;
    cudaGetSymbolAddress((void**)&xnh, g_xn_h);
    cudaGetSymbolAddress((void**)&xnl, g_xn_l);
    cudaGetSymbolAddress((void**)&qwh, g_qw_h);
    cudaGetSymbolAddress((void**)&qwl, g_qw_l);
    cudaGetSymbolAddress((void**)&owh, g_ow_h);
    cudaGetSymbolAddress((void**)&owl, g_ow_l);
    cudaGetSymbolAddress((void**)&cxh, g_cx_h);
    cudaGetSymbolAddress((void**)&cxl, g_cx_l);
    cudaGetSymbolAddress((void**)&qbuf, g_q);
    cudaGetSymbolAddress((void**)&ctxp, g_ctx);

    cudaFuncSetAttribute(gemm3_kernel, cudaFuncAttributeMaxDynamicSharedMemorySize, GEMM_SMEM);
    cudaFuncSetAttribute(attn_mma_kernel, cudaFuncAttributeMaxDynamicSharedMemorySize, ATTN_SMEM);

    rmsnorm_split_kernel<<<MROWS, 256>>>(hidden, pw, xnh, xnl);
    split_kernel<<<(EDIM * EDIM / 4 + 255) / 256, 256>>>(qw, qwh, qwl, EDIM * EDIM / 4);
    split_kernel<<<(EDIM * EDIM / 4 + 255) / 256, 256>>>(ow, owh, owl, EDIM * EDIM / 4);

    gemm3_kernel<<<dim3(16, 32), 256, GEMM_SMEM>>>(xnh, xnl, qwh, qwl, nullptr, qbuf);
    attn_mma_kernel<<<NB * BQ * HKVN * 2, 256, ATTN_SMEM>>>(qbuf, mk, mv, idx, wts, ctxp);
    split_kernel<<<(MROWS * EDIM / 4 + 255) / 256, 256>>>(ctxp, cxh, cxl, MROWS * EDIM / 4);
    gemm3_kernel<<<dim3(16, 32), 256, GEMM_SMEM>>>(cxh, cxl, owh, owl, hidden, out);
}

// round 5
// speedup vs baseline: 3.2822x; 1.4479x over previous
#include <cuda_runtime.h>
#include <cuda_fp16.h>
#include <cstdint>

// ---------------- problem constants ----------------
#define NB    2
#define LSEQ  2048
#define EDIM  2048
#define HKVN  4
#define DH    128
#define SCH   64
#define BQ    32
#define GQ    4
#define KTOP  16
#define MCNK  512
#define MROWS 4096

#define SCALE 0.08838834764831845f

// ---------------- scratch ----------------
__device__ __half g_xn_h[(size_t)MROWS * EDIM];
__device__ __half g_xn_l[(size_t)MROWS * EDIM];
__device__ __half g_qw16[(size_t)EDIM * EDIM];
__device__ __half g_ow16[(size_t)EDIM * EDIM];
__device__ __half g_cx_h[(size_t)MROWS * EDIM];
__device__ __half g_cx_l[(size_t)MROWS * EDIM];
__device__ float  g_q[(size_t)MROWS * EDIM];

// ---------------- helpers ----------------
__device__ __forceinline__ void cp16(uint32_t dst, const void* src) {
    asm volatile("cp.async.cg.shared.global [%0], [%1], 16;\n" :: "r"(dst), "l"(src));
}
__device__ __forceinline__ void ldm_x4(uint32_t* r, uint32_t a) {
    asm volatile("ldmatrix.sync.aligned.m8n8.x4.shared.b16 {%0,%1,%2,%3}, [%4];\n"
                 : "=r"(r[0]), "=r"(r[1]), "=r"(r[2]), "=r"(r[3]) : "r"(a));
}
__device__ __forceinline__ void ldm_x4t(uint32_t* r, uint32_t a) {
    asm volatile("ldmatrix.sync.aligned.m8n8.x4.trans.shared.b16 {%0,%1,%2,%3}, [%4];\n"
                 : "=r"(r[0]), "=r"(r[1]), "=r"(r[2]), "=r"(r[3]) : "r"(a));
}
__device__ __forceinline__ void mma_fp16(float* d, const uint32_t* a, uint32_t b0, uint32_t b1) {
    asm volatile("mma.sync.aligned.m16n8k16.row.col.f32.f16.f16.f32 "
                 "{%0,%1,%2,%3}, {%4,%5,%6,%7}, {%8,%9}, {%0,%1,%2,%3};\n"
                 : "+f"(d[0]), "+f"(d[1]), "+f"(d[2]), "+f"(d[3])
                 : "r"(a[0]), "r"(a[1]), "r"(a[2]), "r"(a[3]), "r"(b0), "r"(b1));
}

// ================= RMSNorm + fp16 split =================
__global__ void rmsnorm_split_kernel(const float* __restrict__ x,
                                     const float* __restrict__ w,
                                     __half* __restrict__ yh,
                                     __half* __restrict__ yl)
{
    int row = blockIdx.x;
    int tid = threadIdx.x;
    const float4* xr = (const float4*)(x + (size_t)row * EDIM);
    const float4* wr = (const float4*)w;
    float4 v0 = xr[tid];
    float4 v1 = xr[tid + 256];
    float ss = v0.x*v0.x + v0.y*v0.y + v0.z*v0.z + v0.w*v0.w
             + v1.x*v1.x + v1.y*v1.y + v1.z*v1.z + v1.w*v1.w;
    #pragma unroll
    for (int o = 16; o > 0; o >>= 1) ss += __shfl_xor_sync(0xffffffffu, ss, o);
    __shared__ float red[8];
    if ((tid & 31) == 0) red[tid >> 5] = ss;
    __syncthreads();
    float tot = red[0] + red[1] + red[2] + red[3] + red[4] + red[5] + red[6] + red[7];
    float inv = rsqrtf(tot * (1.0f / (float)EDIM) + 1e-6f);
    float4 w0 = wr[tid], w1 = wr[tid + 256];
    float o0[4] = { v0.x*inv*w0.x, v0.y*inv*w0.y, v0.z*inv*w0.z, v0.w*inv*w0.w };
    float o1[4] = { v1.x*inv*w1.x, v1.y*inv*w1.y, v1.z*inv*w1.z, v1.w*inv*w1.w };
    size_t base = (size_t)row * EDIM;
    #pragma unroll
    for (int j = 0; j < 4; j++) {
        __half h = __float2half(o0[j]);
        yh[base + tid*4 + j] = h;
        yl[base + tid*4 + j] = __float2half(o0[j] - __half2float(h));
    }
    #pragma unroll
    for (int j = 0; j < 4; j++) {
        __half h = __float2half(o1[j]);
        yh[base + (tid+256)*4 + j] = h;
        yl[base + (tid+256)*4 + j] = __float2half(o1[j] - __half2float(h));
    }
}

// ================= fp32 -> fp16 convert =================
__global__ void cvt_h_kernel(const float* __restrict__ in, __half* __restrict__ o, int n4)
{
    int i = blockIdx.x * blockDim.x + threadIdx.x;
    if (i >= n4) return;
    float4 v = ((const float4*)in)[i];
    __half2 a = __floats2half2_rn(v.x, v.y);
    __half2 b = __floats2half2_rn(v.z, v.w);
    ((uint2*)o)[i] = make_uint2(*(uint32_t*)&a, *(uint32_t*)&b);
}

// ================= fp16 2-pass tensor-core GEMM =================
// C[M,2048] = (Ah+Al)[M,2048] * B16[2048,2048]^T (+Cadd)
// 128x128x32 tiles, 8 warps (2x4), 2-stage cp.async.
// Stage: Ah 10240 | Al 10240 | B 10240 = 30720 B
#define GASTR 80
#define GPL 10240
#define GBOFF 20480
#define GSTAGE 30720
#define GEMM_SMEM (2 * GSTAGE)

__global__ void __launch_bounds__(256, 2) gemm2_kernel(
    const __half* __restrict__ Ah, const __half* __restrict__ Al,
    const __half* __restrict__ B16,
    const float* __restrict__ Cadd, float* __restrict__ C)
{
    extern __shared__ char smem[];
    uint32_t sbase = (uint32_t)__cvta_generic_to_shared(smem);
    int tid = threadIdx.x;
    int bn = blockIdx.x, bm = blockIdx.y;
    int lane = tid & 31;
    int wid = tid >> 5;
    int wm = wid & 1;
    int wn = wid >> 1;

    size_t rowA0 = (size_t)bm * 128;
    size_t rowB0 = (size_t)bn * 128;

    auto load_stage = [&](int kt, int s) {
        uint32_t d0 = sbase + s * GSTAGE;
        #pragma unroll
        for (int ii = 0; ii < 6; ii++) {
            int u = tid + ii * 256;                    // 0..1535 16B units
            const __half* src;
            uint32_t off;
            if (u < 1024) {                            // A planes
                int plane = u >> 9, idx = u & 511;
                int rr = idx >> 2, c4 = idx & 3;
                src = (plane ? Al : Ah) + (rowA0 + rr) * EDIM + kt + c4 * 8;
                off = plane * GPL + rr * GASTR + c4 * 16;
            } else {                                   // B plane
                int idx = u - 1024;
                int rr = idx >> 2, c4 = idx & 3;
                src = B16 + (rowB0 + rr) * EDIM + kt + c4 * 8;
                off = GBOFF + rr * GASTR + c4 * 16;
            }
            cp16(d0 + off, src);
        }
        asm volatile("cp.async.commit_group;\n" ::);
    };

    float acc[4][4][4];
    #pragma unroll
    for (int mi = 0; mi < 4; mi++)
        #pragma unroll
        for (int ni = 0; ni < 4; ni++)
            #pragma unroll
            for (int r = 0; r < 4; r++) acc[mi][ni][r] = 0.0f;

    uint32_t fl = (uint32_t)((lane & 15) * GASTR + (lane >> 4) * 16);
    uint32_t aw = (uint32_t)(wm * 64) * GASTR;
    uint32_t bw = (uint32_t)(wn * 32) * GASTR;

    load_stage(0, 0);

    const int NIT = EDIM / 32;   // 64
    for (int it = 0; it < NIT; it++) {
        if (it + 1 < NIT) {
            load_stage((it + 1) * 32, (it + 1) & 1);
            asm volatile("cp.async.wait_group 1;\n" ::);
        } else {
            asm volatile("cp.async.wait_group 0;\n" ::);
        }
        __syncthreads();

        uint32_t sb = sbase + (it & 1) * GSTAGE;
        #pragma unroll
        for (int ks = 0; ks < 2; ks++) {
            uint32_t bq[2][4];
            #pragma unroll
            for (int np = 0; np < 2; np++)
                ldm_x4(bq[np], sb + GBOFF + bw + (uint32_t)(np * 16) * GASTR + ks * 32 + fl);
            #pragma unroll
            for (int mi = 0; mi < 4; mi++) {
                uint32_t ah[4], al[4];
                uint32_t a0 = sb + aw + (uint32_t)(mi * 16) * GASTR + ks * 32 + fl;
                ldm_x4(ah, a0);
                ldm_x4(al, a0 + GPL);
                #pragma unroll
                for (int ni = 0; ni < 4; ni++) {
                    int np = ni >> 1, sel = ni & 1;
                    uint32_t b0 = bq[np][sel], b1 = bq[np][sel + 2];
                    mma_fp16(acc[mi][ni], ah, b0, b1);
                    mma_fp16(acc[mi][ni], al, b0, b1);
                }
            }
        }
        __syncthreads();
    }

    int r0 = bm * 128 + wm * 64 + (lane >> 2);
    int c0 = bn * 128 + wn * 32 + (lane & 3) * 2;
    #pragma unroll
    for (int mi = 0; mi < 4; mi++)
        #pragma unroll
        for (int ni = 0; ni < 4; ni++) {
            int rr = r0 + mi * 16;
            int cc = c0 + ni * 8;
            float2 v0 = { acc[mi][ni][0], acc[mi][ni][1] };
            float2 v1 = { acc[mi][ni][2], acc[mi][ni][3] };
            if (Cadd) {
                float2 a0 = *(const float2*)(Cadd + (size_t)rr * EDIM + cc);
                float2 a1 = *(const float2*)(Cadd + (size_t)(rr + 8) * EDIM + cc);
                v0.x += a0.x; v0.y += a0.y;
                v1.x += a1.x; v1.y += a1.y;
            }
            *(float2*)(C + (size_t)rr * EDIM + cc) = v0;
            *(float2*)(C + (size_t)(rr + 8) * EDIM + cc) = v1;
        }
}

// ================= Attention (fp16 2-pass HMMA) =================
// planes: Q single | Kh/V | Kl | Ph | Pl  (5 planes)
#define KSTRB 272
#define PLB   (128 * KSTRB)
#define REG_Q  0
#define REG_KV PLB            // Kh (QK phase) / V (PV phase)
#define REG_KL (2 * PLB)      // Kl
#define REG_PH (3 * PLB)
#define REG_PL (4 * PLB)
#define ATTN_SMEM (5 * PLB)   // 174080

__global__ void __launch_bounds__(256, 1) attn_fp16_kernel(
    const float* __restrict__ q,
    const float* __restrict__ mk,
    const float* __restrict__ mv,
    const int* __restrict__ idxs,
    const float* __restrict__ wts,
    __half* __restrict__ cxh,
    __half* __restrict__ cxl)
{
    extern __shared__ char sm[];
    uint32_t sb = (uint32_t)__cvta_generic_to_shared(sm);

    __shared__ int   s_idx[KTOP];
    __shared__ float s_w[KTOP];
    __shared__ float s_mx[128][4];
    __shared__ float s_sm[128][4];

    int tid = threadIdx.x;
    int lane = tid & 31;
    int wid = tid >> 5;
    int wm = wid & 1;
    int wn = wid >> 1;

    int bid = blockIdx.x;
    int gp = bid & 1;
    int h  = (bid >> 1) & 3;
    int b  = (bid >> 3) & 31;
    int n  = bid >> 8;

    int row0 = n * LSEQ + b * SCH;
    int col0 = h * (GQ * DH) + gp * 256;

    if (tid < KTOP) {
        int off = ((n * BQ + b) * HKVN + h) * KTOP + tid;
        s_idx[tid] = idxs[off];
        s_w[tid]   = wts[off];
    }

    // ---- Q load (single fp16 plane) ----
    #pragma unroll
    for (int it = 0; it < 16; ++it) {
        int u = tid + it * 256;
        int m = u >> 5;
        int d4 = (u & 31) << 2;
        int s_ = m & 63;
        int gi = m >> 6;
        float4 v = *(const float4*)(q + (size_t)(row0 + s_) * EDIM + col0 + gi * DH + d4);
        char* hb = sm + REG_Q + m * KSTRB + d4 * 2;
        ((__half2*)hb)[0] = __floats2half2_rn(v.x, v.y);
        ((__half2*)hb)[1] = __floats2half2_rn(v.z, v.w);
    }

    float cacc[4][4][4];
    #pragma unroll
    for (int mi = 0; mi < 4; mi++)
        #pragma unroll
        for (int ni = 0; ni < 4; ni++)
            #pragma unroll
            for (int r = 0; r < 4; r++) cacc[mi][ni][r] = 0.0f;

    uint32_t fl = (uint32_t)((lane & 15) * KSTRB + (lane >> 4) * 16);
    uint32_t qa  = sb + REG_Q  + (uint32_t)(wm * 64) * KSTRB + fl;
    uint32_t pha = sb + REG_PH + (uint32_t)(wm * 64) * KSTRB + fl;
    uint32_t kb  = sb + REG_KV + (uint32_t)(wn * 32) * KSTRB + fl;

    __syncthreads();

    for (int cp = 0; cp < 8; ++cp) {
        // ---- K pair load + fp16 split ----
        #pragma unroll
        for (int it = 0; it < 16; ++it) {
            int u = tid + it * 256;
            int nr = u >> 5;
            int d4 = (u & 31) << 2;
            int c = 2 * cp + (nr >> 6);
            int j = nr & 63;
            int ci = s_idx[c];
            size_t base = ((size_t)(n * (MCNK * SCH) + ci * SCH + j) * HKVN + h) * DH;
            float4 v = *(const float4*)(mk + base + d4);
            char* hb = sm + REG_KV + nr * KSTRB + d4 * 2;
            __half hx = __float2half(v.x), hy = __float2half(v.y);
            __half hz = __float2half(v.z), hw = __float2half(v.w);
            ((__half2*)hb)[0] = __half2(hx, hy);
            ((__half2*)hb)[1] = __half2(hz, hw);
            char* lb = hb + PLB;  // REG_KL
            ((__half2*)lb)[0] = __floats2half2_rn(v.x - __half2float(hx), v.y - __half2float(hy));
            ((__half2*)lb)[1] = __floats2half2_rn(v.z - __half2float(hz), v.w - __half2float(hw));
        }
        __syncthreads();

        // ---- QK^T: Q*(Kh+Kl), 2 passes ----
        float sacc[4][4][4];
        #pragma unroll
        for (int mi = 0; mi < 4; mi++)
            #pragma unroll
            for (int ni = 0; ni < 4; ni++)
                #pragma unroll
                for (int r = 0; r < 4; r++) sacc[mi][ni][r] = 0.0f;

        #pragma unroll
        for (int ks = 0; ks < 8; ks++) {
            uint32_t kh[2][4], kl[2][4];
            #pragma unroll
            for (int np = 0; np < 2; np++) {
                uint32_t b0 = kb + (uint32_t)(np * 16) * KSTRB + ks * 32;
                ldm_x4(kh[np], b0);
                ldm_x4(kl[np], b0 + PLB);
            }
            #pragma unroll
            for (int mi = 0; mi < 4; mi++) {
                uint32_t qf[4];
                ldm_x4(qf, qa + (uint32_t)(mi * 16) * KSTRB + ks * 32);
                #pragma unroll
                for (int ni = 0; ni < 4; ni++) {
                    int np = ni >> 1, sel = ni & 1;
                    mma_fp16(sacc[mi][ni], qf, kh[np][sel], kh[np][sel + 2]);
                    mma_fp16(sacc[mi][ni], qf, kl[np][sel], kl[np][sel + 2]);
                }
            }
        }

        // ---- softmax1 ----
        int rt = wm * 64 + (lane >> 2);
        #pragma unroll
        for (int mi = 0; mi < 4; mi++) {
            float mt = -1e30f, mb = -1e30f;
            #pragma unroll
            for (int ni = 0; ni < 4; ni++) {
                mt = fmaxf(mt, fmaxf(sacc[mi][ni][0], sacc[mi][ni][1]));
                mb = fmaxf(mb, fmaxf(sacc[mi][ni][2], sacc[mi][ni][3]));
            }
            mt = fmaxf(mt, __shfl_xor_sync(0xffffffffu, mt, 1));
            mt = fmaxf(mt, __shfl_xor_sync(0xffffffffu, mt, 2));
            mb = fmaxf(mb, __shfl_xor_sync(0xffffffffu, mb, 1));
            mb = fmaxf(mb, __shfl_xor_sync(0xffffffffu, mb, 2));
            if ((lane & 3) == 0) {
                s_mx[rt + mi * 16][wn] = mt;
                s_mx[rt + mi * 16 + 8][wn] = mb;
            }
        }
        __syncthreads();
        #pragma unroll
        for (int mi = 0; mi < 4; mi++) {
            int r1 = rt + mi * 16, r2 = r1 + 8;
            float mt = fmaxf(fmaxf(s_mx[r1][wn], s_mx[r1][wn ^ 1]), 0.0f);
            float mb = fmaxf(fmaxf(s_mx[r2][wn], s_mx[r2][wn ^ 1]), 0.0f);
            float st = 0.0f, sbt = 0.0f;
            #pragma unroll
            for (int ni = 0; ni < 4; ni++) {
                float e0 = __expf(sacc[mi][ni][0] * SCALE - mt);
                float e1 = __expf(sacc[mi][ni][1] * SCALE - mt);
                float e2 = __expf(sacc[mi][ni][2] * SCALE - mb);
                float e3 = __expf(sacc[mi][ni][3] * SCALE - mb);
                sacc[mi][ni][0] = e0; sacc[mi][ni][1] = e1;
                sacc[mi][ni][2] = e2; sacc[mi][ni][3] = e3;
                st += e0 + e1; sbt += e2 + e3;
            }
            st += __shfl_xor_sync(0xffffffffu, st, 1);
            st += __shfl_xor_sync(0xffffffffu, st, 2);
            sbt += __shfl_xor_sync(0xffffffffu, sbt, 1);
            sbt += __shfl_xor_sync(0xffffffffu, sbt, 2);
            if ((lane & 3) == 0) {
                s_sm[r1][wn] = st;
                s_sm[r2][wn] = sbt;
            }
        }
        __syncthreads();
        // ---- normalize, fold weight, split-write P planes ----
        float wgt = s_w[2 * cp + (wn >> 1)];
        #pragma unroll
        for (int mi = 0; mi < 4; mi++) {
            int r1 = rt + mi * 16, r2 = r1 + 8;
            float mt = fmaxf(fmaxf(s_mx[r1][wn], s_mx[r1][wn ^ 1]), 0.0f);
            float mb = fmaxf(fmaxf(s_mx[r2][wn], s_mx[r2][wn ^ 1]), 0.0f);
            float sc1 = wgt / (s_sm[r1][wn] + s_sm[r1][wn ^ 1] + __expf(-mt));
            float sc2 = wgt / (s_sm[r2][wn] + s_sm[r2][wn ^ 1] + __expf(-mb));
            #pragma unroll
            for (int ni = 0; ni < 4; ni++) {
                float p0 = sacc[mi][ni][0] * sc1, p1 = sacc[mi][ni][1] * sc1;
                float p2 = sacc[mi][ni][2] * sc2, p3 = sacc[mi][ni][3] * sc2;
                int cbyte = (wn * 32 + ni * 8 + (lane & 3) * 2) * 2;
                char* h1 = sm + REG_PH + r1 * KSTRB + cbyte;
                char* h2 = sm + REG_PH + r2 * KSTRB + cbyte;
                __half q0 = __float2half(p0), q1 = __float2half(p1);
                __half q2 = __float2half(p2), q3 = __float2half(p3);
                *(__half2*)h1 = __half2(q0, q1);
                *(__half2*)h2 = __half2(q2, q3);
                *(__half2*)(h1 + PLB) = __floats2half2_rn(p0 - __half2float(q0), p1 - __half2float(q1));
                *(__half2*)(h2 + PLB) = __floats2half2_rn(p2 - __half2float(q2), p3 - __half2float(q3));
            }
        }
        __syncthreads();

        // ---- V pair load (single fp16, overwrites Kh plane) ----
        #pragma unroll
        for (int it = 0; it < 16; ++it) {
            int u = tid + it * 256;
            int nr = u >> 5;
            int d4 = (u & 31) << 2;
            int c = 2 * cp + (nr >> 6);
            int j = nr & 63;
            int ci = s_idx[c];
            size_t base = ((size_t)(n * (MCNK * SCH) + ci * SCH + j) * HKVN + h) * DH;
            float4 v = *(const float4*)(mv + base + d4);
            char* hb = sm + REG_KV + nr * KSTRB + d4 * 2;
            ((__half2*)hb)[0] = __floats2half2_rn(v.x, v.y);
            ((__half2*)hb)[1] = __floats2half2_rn(v.z, v.w);
        }
        __syncthreads();

        // ---- PV: (Ph+Pl)*V, 2 passes ----
        #pragma unroll
        for (int ks = 0; ks < 8; ks++) {
            uint32_t vf[2][4];
            #pragma unroll
            for (int np = 0; np < 2; np++)
                ldm_x4t(vf[np], sb + REG_KV + (uint32_t)(ks * 16) * KSTRB + wn * 64 + np * 32 + fl);
            #pragma unroll
            for (int mi = 0; mi < 4; mi++) {
                uint32_t ph[4], pl[4];
                uint32_t a0 = pha + (uint32_t)(mi * 16) * KSTRB + ks * 32;
                ldm_x4(ph, a0);
                ldm_x4(pl, a0 + PLB);
                #pragma unroll
                for (int ni = 0; ni < 4; ni++) {
                    int np = ni >> 1, sel = ni & 1;
                    uint32_t b0 = vf[np][sel * 2], b1 = vf[np][sel * 2 + 1];
                    mma_fp16(cacc[mi][ni], ph, b0, b1);
                    mma_fp16(cacc[mi][ni], pl, b0, b1);
                }
            }
        }
        __syncthreads();
    }

    // ---- epilogue: split ctx to fp16 hi/lo planes ----
    #pragma unroll
    for (int mi = 0; mi < 4; mi++) {
        #pragma unroll
        for (int ni = 0; ni < 4; ni++) {
            int r1 = wm * 64 + mi * 16 + (lane >> 2);
            int cc = wn * 32 + ni * 8 + (lane & 3) * 2;
            #pragma unroll
            for (int half = 0; half < 2; half++) {
                int m = r1 + half * 8;
                int s_ = m & 63;
                int gi = m >> 6;
                float v0 = cacc[mi][ni][half * 2], v1 = cacc[mi][ni][half * 2 + 1];
                size_t off = (size_t)(row0 + s_) * EDIM + col0 + gi * DH + cc;
                __half h0 = __float2half(v0), h1 = __float2half(v1);
                *(__half2*)(cxh + off) = __half2(h0, h1);
                *(__half2*)(cxl + off) = __floats2half2_rn(v0 - __half2float(h0), v1 - __half2float(h1));
            }
        }
    }
}

// ================= launch =================
extern "C" void kernel_launch(void* const* d_in, const int* in_sizes, int n_in,
                              void* d_out, int out_size)
{
    const float* hidden = (const float*)d_in[0];
    const float* wts    = (const float*)d_in[1];
    const float* mk     = (const float*)d_in[2];
    const float* mv     = (const float*)d_in[3];
    const int*   idx    = (const int*)d_in[4];
    const float* pw     = (const float*)d_in[5];
    const float* qw     = (const float*)d_in[6];
    const float* ow     = (const float*)d_in[7];
    float* out = (float*)d_out;

    __half *xnh, *xnl, *qw16, *ow16, *cxh, *cxl;
    float *qbuf;
    cudaGetSymbolAddress((void**)&xnh, g_xn_h);
    cudaGetSymbolAddress((void**)&xnl, g_xn_l);
    cudaGetSymbolAddress((void**)&qw16, g_qw16);
    cudaGetSymbolAddress((void**)&ow16, g_ow16);
    cudaGetSymbolAddress((void**)&cxh, g_cx_h);
    cudaGetSymbolAddress((void**)&cxl, g_cx_l);
    cudaGetSymbolAddress((void**)&qbuf, g_q);

    cudaFuncSetAttribute(gemm2_kernel, cudaFuncAttributeMaxDynamicSharedMemorySize, GEMM_SMEM);
    cudaFuncSetAttribute(attn_fp16_kernel, cudaFuncAttributeMaxDynamicSharedMemorySize, ATTN_SMEM);

    rmsnorm_split_kernel<<<MROWS, 256>>>(hidden, pw, xnh, xnl);
    cvt_h_kernel<<<(EDIM * EDIM / 4 + 255) / 256, 256>>>(qw, qw16, EDIM * EDIM / 4);
    cvt_h_kernel<<<(EDIM * EDIM / 4 + 255) / 256, 256>>>(ow, ow16, EDIM * EDIM / 4);

    gemm2_kernel<<<dim3(16, 32), 256, GEMM_SMEM>>>(xnh, xnl, qw16, nullptr, qbuf);
    attn_fp16_kernel<<<NB * BQ * HKVN * 2, 256, ATTN_SMEM>>>(qbuf, mk, mv, idx, wts, cxh, cxl);
    gemm2_kernel<<<dim3(16, 32), 256, GEMM_SMEM>>>(cxh, cxl, ow16, hidden, out);
}

// round 6
// speedup vs baseline: 4.8551x; 1.4792x over previous
#include <cuda_runtime.h>
#include <cuda_fp16.h>
#include <cstdint>

// ---------------- problem constants ----------------
#define NB    2
#define LSEQ  2048
#define EDIM  2048
#define HKVN  4
#define DH    128
#define SCH   64
#define BQ    32
#define GQ    4
#define KTOP  16
#define MCNK  512
#define MROWS 4096

#define SCALE 0.08838834764831845f

// ---------------- scratch ----------------
__device__ __half g_xn[(size_t)MROWS * EDIM];
__device__ __half g_qw16[(size_t)EDIM * EDIM];
__device__ __half g_ow16[(size_t)EDIM * EDIM];
__device__ __half g_cx[(size_t)MROWS * EDIM];
__device__ float  g_q[(size_t)MROWS * EDIM];

// ---------------- helpers ----------------
__device__ __forceinline__ void cp16(uint32_t dst, const void* src) {
    asm volatile("cp.async.cg.shared.global [%0], [%1], 16;\n" :: "r"(dst), "l"(src));
}
__device__ __forceinline__ void ldm_x4(uint32_t* r, uint32_t a) {
    asm volatile("ldmatrix.sync.aligned.m8n8.x4.shared.b16 {%0,%1,%2,%3}, [%4];\n"
                 : "=r"(r[0]), "=r"(r[1]), "=r"(r[2]), "=r"(r[3]) : "r"(a));
}
__device__ __forceinline__ void ldm_x4t(uint32_t* r, uint32_t a) {
    asm volatile("ldmatrix.sync.aligned.m8n8.x4.trans.shared.b16 {%0,%1,%2,%3}, [%4];\n"
                 : "=r"(r[0]), "=r"(r[1]), "=r"(r[2]), "=r"(r[3]) : "r"(a));
}
__device__ __forceinline__ void mma_fp16(float* d, const uint32_t* a, uint32_t b0, uint32_t b1) {
    asm volatile("mma.sync.aligned.m16n8k16.row.col.f32.f16.f16.f32 "
                 "{%0,%1,%2,%3}, {%4,%5,%6,%7}, {%8,%9}, {%0,%1,%2,%3};\n"
                 : "+f"(d[0]), "+f"(d[1]), "+f"(d[2]), "+f"(d[3])
                 : "r"(a[0]), "r"(a[1]), "r"(a[2]), "r"(a[3]), "r"(b0), "r"(b1));
}

// ================= RMSNorm -> fp16 =================
__global__ void rmsnorm_h_kernel(const float* __restrict__ x,
                                 const float* __restrict__ w,
                                 __half* __restrict__ y)
{
    int row = blockIdx.x;
    int tid = threadIdx.x;
    const float4* xr = (const float4*)(x + (size_t)row * EDIM);
    const float4* wr = (const float4*)w;
    float4 v0 = xr[tid];
    float4 v1 = xr[tid + 256];
    float ss = v0.x*v0.x + v0.y*v0.y + v0.z*v0.z + v0.w*v0.w
             + v1.x*v1.x + v1.y*v1.y + v1.z*v1.z + v1.w*v1.w;
    #pragma unroll
    for (int o = 16; o > 0; o >>= 1) ss += __shfl_xor_sync(0xffffffffu, ss, o);
    __shared__ float red[8];
    if ((tid & 31) == 0) red[tid >> 5] = ss;
    __syncthreads();
    float tot = red[0] + red[1] + red[2] + red[3] + red[4] + red[5] + red[6] + red[7];
    float inv = rsqrtf(tot * (1.0f / (float)EDIM) + 1e-6f);
    float4 w0 = wr[tid], w1 = wr[tid + 256];
    __half2 a = __floats2half2_rn(v0.x*inv*w0.x, v0.y*inv*w0.y);
    __half2 b = __floats2half2_rn(v0.z*inv*w0.z, v0.w*inv*w0.w);
    __half2 c = __floats2half2_rn(v1.x*inv*w1.x, v1.y*inv*w1.y);
    __half2 d = __floats2half2_rn(v1.z*inv*w1.z, v1.w*inv*w1.w);
    uint2* yr = (uint2*)(y + (size_t)row * EDIM);
    yr[tid] = make_uint2(*(uint32_t*)&a, *(uint32_t*)&b);
    yr[tid + 256] = make_uint2(*(uint32_t*)&c, *(uint32_t*)&d);
}

// ================= fp32 -> fp16 convert =================
__global__ void cvt_h_kernel(const float* __restrict__ in, __half* __restrict__ o, int n4)
{
    int i = blockIdx.x * blockDim.x + threadIdx.x;
    if (i >= n4) return;
    float4 v = ((const float4*)in)[i];
    __half2 a = __floats2half2_rn(v.x, v.y);
    __half2 b = __floats2half2_rn(v.z, v.w);
    ((uint2*)o)[i] = make_uint2(*(uint32_t*)&a, *(uint32_t*)&b);
}

// ================= fp16 single-pass GEMM, 4-stage pipeline =================
// C[M,2048] = A16[M,2048] * B16[2048,2048]^T (+Cadd)
// 128x128x32 tiles, 8 warps (2x4), 4-stage cp.async, ONE sync per iteration.
// Stage: A 10240 | B 10240 = 20480 B  (80B padded rows, 64B data)
#define GASTR 80
#define GBOFF 10240
#define GSTAGE 20480
#define GEMM_SMEM (4 * GSTAGE)

__global__ void __launch_bounds__(256, 2) gemm1_kernel(
    const __half* __restrict__ A16,
    const __half* __restrict__ B16,
    const float* __restrict__ Cadd, float* __restrict__ C)
{
    extern __shared__ char smem[];
    uint32_t sbase = (uint32_t)__cvta_generic_to_shared(smem);
    int tid = threadIdx.x;
    int bn = blockIdx.x, bm = blockIdx.y;
    int lane = tid & 31;
    int wid = tid >> 5;
    int wm = wid & 1;
    int wn = wid >> 1;

    size_t rowA0 = (size_t)bm * 128;
    size_t rowB0 = (size_t)bn * 128;

    auto load_stage = [&](int kt, int s) {
        uint32_t d0 = sbase + s * GSTAGE;
        #pragma unroll
        for (int ii = 0; ii < 4; ii++) {
            int u = tid + ii * 256;                    // 0..1023 16B units
            int rr = (u >> 2) & 127, c4 = u & 3;
            const __half* src;
            uint32_t off;
            if (u < 512) {
                src = A16 + (rowA0 + rr) * EDIM + kt + c4 * 8;
                off = rr * GASTR + c4 * 16;
            } else {
                src = B16 + (rowB0 + rr) * EDIM + kt + c4 * 8;
                off = GBOFF + rr * GASTR + c4 * 16;
            }
            cp16(d0 + off, src);
        }
        asm volatile("cp.async.commit_group;\n" ::);
    };

    float acc[4][4][4];
    #pragma unroll
    for (int mi = 0; mi < 4; mi++)
        #pragma unroll
        for (int ni = 0; ni < 4; ni++)
            #pragma unroll
            for (int r = 0; r < 4; r++) acc[mi][ni][r] = 0.0f;

    uint32_t fl = (uint32_t)((lane & 15) * GASTR + (lane >> 4) * 16);
    uint32_t aw = (uint32_t)(wm * 64) * GASTR;
    uint32_t bw = (uint32_t)(wn * 32) * GASTR;

    load_stage(0, 0);
    load_stage(32, 1);
    load_stage(64, 2);

    const int NIT = EDIM / 32;   // 64
    for (int it = 0; it < NIT; it++) {
        if (it + 2 < NIT)      { asm volatile("cp.async.wait_group 2;\n" ::); }
        else if (it + 1 < NIT) { asm volatile("cp.async.wait_group 1;\n" ::); }
        else                   { asm volatile("cp.async.wait_group 0;\n" ::); }
        __syncthreads();
        if (it + 3 < NIT) load_stage((it + 3) * 32, (it + 3) & 3);

        uint32_t sb = sbase + (it & 3) * GSTAGE;
        #pragma unroll
        for (int ks = 0; ks < 2; ks++) {
            uint32_t bq[2][4];
            #pragma unroll
            for (int np = 0; np < 2; np++)
                ldm_x4(bq[np], sb + GBOFF + bw + (uint32_t)(np * 16) * GASTR + ks * 32 + fl);
            #pragma unroll
            for (int mi = 0; mi < 4; mi++) {
                uint32_t af[4];
                ldm_x4(af, sb + aw + (uint32_t)(mi * 16) * GASTR + ks * 32 + fl);
                #pragma unroll
                for (int ni = 0; ni < 4; ni++) {
                    int np = ni >> 1, sel = ni & 1;
                    mma_fp16(acc[mi][ni], af, bq[np][sel], bq[np][sel + 2]);
                }
            }
        }
    }

    int r0 = bm * 128 + wm * 64 + (lane >> 2);
    int c0 = bn * 128 + wn * 32 + (lane & 3) * 2;
    #pragma unroll
    for (int mi = 0; mi < 4; mi++)
        #pragma unroll
        for (int ni = 0; ni < 4; ni++) {
            int rr = r0 + mi * 16;
            int cc = c0 + ni * 8;
            float2 v0 = { acc[mi][ni][0], acc[mi][ni][1] };
            float2 v1 = { acc[mi][ni][2], acc[mi][ni][3] };
            if (Cadd) {
                float2 a0 = *(const float2*)(Cadd + (size_t)rr * EDIM + cc);
                float2 a1 = *(const float2*)(Cadd + (size_t)(rr + 8) * EDIM + cc);
                v0.x += a0.x; v0.y += a0.y;
                v1.x += a1.x; v1.y += a1.y;
            }
            *(float2*)(C + (size_t)rr * EDIM + cc) = v0;
            *(float2*)(C + (size_t)(rr + 8) * EDIM + cc) = v1;
        }
}

// ================= Attention (fp16; QK single-pass, PV P-split) =================
// planes: Q | KV (K or V) | Ph | Pl
#define KSTRB 272
#define PLB   (128 * KSTRB)
#define REG_Q  0
#define REG_KV PLB
#define REG_PH (2 * PLB)
#define REG_PL (3 * PLB)
#define ATTN_SMEM (4 * PLB)   // 139264

__global__ void __launch_bounds__(256, 1) attn_fp16_kernel(
    const float* __restrict__ q,
    const float* __restrict__ mk,
    const float* __restrict__ mv,
    const int* __restrict__ idxs,
    const float* __restrict__ wts,
    __half* __restrict__ cx)
{
    extern __shared__ char sm[];
    uint32_t sb = (uint32_t)__cvta_generic_to_shared(sm);

    __shared__ int   s_idx[KTOP];
    __shared__ float s_w[KTOP];
    __shared__ float s_mx[128][4];
    __shared__ float s_sm[128][4];

    int tid = threadIdx.x;
    int lane = tid & 31;
    int wid = tid >> 5;
    int wm = wid & 1;
    int wn = wid >> 1;

    int bid = blockIdx.x;
    int gp = bid & 1;
    int h  = (bid >> 1) & 3;
    int b  = (bid >> 3) & 31;
    int n  = bid >> 8;

    int row0 = n * LSEQ + b * SCH;
    int col0 = h * (GQ * DH) + gp * 256;

    if (tid < KTOP) {
        int off = ((n * BQ + b) * HKVN + h) * KTOP + tid;
        s_idx[tid] = idxs[off];
        s_w[tid]   = wts[off];
    }

    // ---- Q load ----
    #pragma unroll
    for (int it = 0; it < 16; ++it) {
        int u = tid + it * 256;
        int m = u >> 5;
        int d4 = (u & 31) << 2;
        int s_ = m & 63;
        int gi = m >> 6;
        float4 v = *(const float4*)(q + (size_t)(row0 + s_) * EDIM + col0 + gi * DH + d4);
        char* hb = sm + REG_Q + m * KSTRB + d4 * 2;
        ((__half2*)hb)[0] = __floats2half2_rn(v.x, v.y);
        ((__half2*)hb)[1] = __floats2half2_rn(v.z, v.w);
    }

    float cacc[4][4][4];
    #pragma unroll
    for (int mi = 0; mi < 4; mi++)
        #pragma unroll
        for (int ni = 0; ni < 4; ni++)
            #pragma unroll
            for (int r = 0; r < 4; r++) cacc[mi][ni][r] = 0.0f;

    uint32_t fl = (uint32_t)((lane & 15) * KSTRB + (lane >> 4) * 16);
    uint32_t qa  = sb + REG_Q  + (uint32_t)(wm * 64) * KSTRB + fl;
    uint32_t pha = sb + REG_PH + (uint32_t)(wm * 64) * KSTRB + fl;
    uint32_t kb  = sb + REG_KV + (uint32_t)(wn * 32) * KSTRB + fl;

    __syncthreads();

    for (int cp = 0; cp < 8; ++cp) {
        // ---- K pair load (single fp16) ----
        #pragma unroll
        for (int it = 0; it < 16; ++it) {
            int u = tid + it * 256;
            int nr = u >> 5;
            int d4 = (u & 31) << 2;
            int c = 2 * cp + (nr >> 6);
            int j = nr & 63;
            int ci = s_idx[c];
            size_t base = ((size_t)(n * (MCNK * SCH) + ci * SCH + j) * HKVN + h) * DH;
            float4 v = *(const float4*)(mk + base + d4);
            char* hb = sm + REG_KV + nr * KSTRB + d4 * 2;
            ((__half2*)hb)[0] = __floats2half2_rn(v.x, v.y);
            ((__half2*)hb)[1] = __floats2half2_rn(v.z, v.w);
        }
        __syncthreads();

        // ---- QK^T single pass ----
        float sacc[4][4][4];
        #pragma unroll
        for (int mi = 0; mi < 4; mi++)
            #pragma unroll
            for (int ni = 0; ni < 4; ni++)
                #pragma unroll
                for (int r = 0; r < 4; r++) sacc[mi][ni][r] = 0.0f;

        #pragma unroll
        for (int ks = 0; ks < 8; ks++) {
            uint32_t kh[2][4];
            #pragma unroll
            for (int np = 0; np < 2; np++)
                ldm_x4(kh[np], kb + (uint32_t)(np * 16) * KSTRB + ks * 32);
            #pragma unroll
            for (int mi = 0; mi < 4; mi++) {
                uint32_t qf[4];
                ldm_x4(qf, qa + (uint32_t)(mi * 16) * KSTRB + ks * 32);
                #pragma unroll
                for (int ni = 0; ni < 4; ni++) {
                    int np = ni >> 1, sel = ni & 1;
                    mma_fp16(sacc[mi][ni], qf, kh[np][sel], kh[np][sel + 2]);
                }
            }
        }

        // ---- softmax1 ----
        int rt = wm * 64 + (lane >> 2);
        #pragma unroll
        for (int mi = 0; mi < 4; mi++) {
            float mt = -1e30f, mb = -1e30f;
            #pragma unroll
            for (int ni = 0; ni < 4; ni++) {
                mt = fmaxf(mt, fmaxf(sacc[mi][ni][0], sacc[mi][ni][1]));
                mb = fmaxf(mb, fmaxf(sacc[mi][ni][2], sacc[mi][ni][3]));
            }
            mt = fmaxf(mt, __shfl_xor_sync(0xffffffffu, mt, 1));
            mt = fmaxf(mt, __shfl_xor_sync(0xffffffffu, mt, 2));
            mb = fmaxf(mb, __shfl_xor_sync(0xffffffffu, mb, 1));
            mb = fmaxf(mb, __shfl_xor_sync(0xffffffffu, mb, 2));
            if ((lane & 3) == 0) {
                s_mx[rt + mi * 16][wn] = mt;
                s_mx[rt + mi * 16 + 8][wn] = mb;
            }
        }
        __syncthreads();
        #pragma unroll
        for (int mi = 0; mi < 4; mi++) {
            int r1 = rt + mi * 16, r2 = r1 + 8;
            float mt = fmaxf(fmaxf(s_mx[r1][wn], s_mx[r1][wn ^ 1]), 0.0f);
            float mb = fmaxf(fmaxf(s_mx[r2][wn], s_mx[r2][wn ^ 1]), 0.0f);
            float st = 0.0f, sbt = 0.0f;
            #pragma unroll
            for (int ni = 0; ni < 4; ni++) {
                float e0 = __expf(sacc[mi][ni][0] * SCALE - mt);
                float e1 = __expf(sacc[mi][ni][1] * SCALE - mt);
                float e2 = __expf(sacc[mi][ni][2] * SCALE - mb);
                float e3 = __expf(sacc[mi][ni][3] * SCALE - mb);
                sacc[mi][ni][0] = e0; sacc[mi][ni][1] = e1;
                sacc[mi][ni][2] = e2; sacc[mi][ni][3] = e3;
                st += e0 + e1; sbt += e2 + e3;
            }
            st += __shfl_xor_sync(0xffffffffu, st, 1);
            st += __shfl_xor_sync(0xffffffffu, st, 2);
            sbt += __shfl_xor_sync(0xffffffffu, sbt, 1);
            sbt += __shfl_xor_sync(0xffffffffu, sbt, 2);
            if ((lane & 3) == 0) {
                s_sm[r1][wn] = st;
                s_sm[r2][wn] = sbt;
            }
        }
        __syncthreads();
        // ---- normalize, fold weight, split-write P planes ----
        float wgt = s_w[2 * cp + (wn >> 1)];
        #pragma unroll
        for (int mi = 0; mi < 4; mi++) {
            int r1 = rt + mi * 16, r2 = r1 + 8;
            float mt = fmaxf(fmaxf(s_mx[r1][wn], s_mx[r1][wn ^ 1]), 0.0f);
            float mb = fmaxf(fmaxf(s_mx[r2][wn], s_mx[r2][wn ^ 1]), 0.0f);
            float sc1 = wgt / (s_sm[r1][wn] + s_sm[r1][wn ^ 1] + __expf(-mt));
            float sc2 = wgt / (s_sm[r2][wn] + s_sm[r2][wn ^ 1] + __expf(-mb));
            #pragma unroll
            for (int ni = 0; ni < 4; ni++) {
                float p0 = sacc[mi][ni][0] * sc1, p1 = sacc[mi][ni][1] * sc1;
                float p2 = sacc[mi][ni][2] * sc2, p3 = sacc[mi][ni][3] * sc2;
                int cbyte = (wn * 32 + ni * 8 + (lane & 3) * 2) * 2;
                char* h1 = sm + REG_PH + r1 * KSTRB + cbyte;
                char* h2 = sm + REG_PH + r2 * KSTRB + cbyte;
                __half q0 = __float2half(p0), q1 = __float2half(p1);
                __half q2 = __float2half(p2), q3 = __float2half(p3);
                *(__half2*)h1 = __half2(q0, q1);
                *(__half2*)h2 = __half2(q2, q3);
                *(__half2*)(h1 + PLB) = __floats2half2_rn(p0 - __half2float(q0), p1 - __half2float(q1));
                *(__half2*)(h2 + PLB) = __floats2half2_rn(p2 - __half2float(q2), p3 - __half2float(q3));
            }
        }
        __syncthreads();

        // ---- V pair load (single fp16, overwrites K plane) ----
        #pragma unroll
        for (int it = 0; it < 16; ++it) {
            int u = tid + it * 256;
            int nr = u >> 5;
            int d4 = (u & 31) << 2;
            int c = 2 * cp + (nr >> 6);
            int j = nr & 63;
            int ci = s_idx[c];
            size_t base = ((size_t)(n * (MCNK * SCH) + ci * SCH + j) * HKVN + h) * DH;
            float4 v = *(const float4*)(mv + base + d4);
            char* hb = sm + REG_KV + nr * KSTRB + d4 * 2;
            ((__half2*)hb)[0] = __floats2half2_rn(v.x, v.y);
            ((__half2*)hb)[1] = __floats2half2_rn(v.z, v.w);
        }
        __syncthreads();

        // ---- PV: (Ph+Pl)*V ----
        #pragma unroll
        for (int ks = 0; ks < 8; ks++) {
            uint32_t vf[2][4];
            #pragma unroll
            for (int np = 0; np < 2; np++)
                ldm_x4t(vf[np], sb + REG_KV + (uint32_t)(ks * 16) * KSTRB + wn * 64 + np * 32 + fl);
            #pragma unroll
            for (int mi = 0; mi < 4; mi++) {
                uint32_t ph[4], pl[4];
                uint32_t a0 = pha + (uint32_t)(mi * 16) * KSTRB + ks * 32;
                ldm_x4(ph, a0);
                ldm_x4(pl, a0 + PLB);
                #pragma unroll
                for (int ni = 0; ni < 4; ni++) {
                    int np = ni >> 1, sel = ni & 1;
                    uint32_t b0 = vf[np][sel * 2], b1 = vf[np][sel * 2 + 1];
                    mma_fp16(cacc[mi][ni], ph, b0, b1);
                    mma_fp16(cacc[mi][ni], pl, b0, b1);
                }
            }
        }
        __syncthreads();
    }

    // ---- epilogue: ctx -> fp16 ----
    #pragma unroll
    for (int mi = 0; mi < 4; mi++) {
        #pragma unroll
        for (int ni = 0; ni < 4; ni++) {
            int r1 = wm * 64 + mi * 16 + (lane >> 2);
            int cc = wn * 32 + ni * 8 + (lane & 3) * 2;
            #pragma unroll
            for (int half = 0; half < 2; half++) {
                int m = r1 + half * 8;
                int s_ = m & 63;
                int gi = m >> 6;
                size_t off = (size_t)(row0 + s_) * EDIM + col0 + gi * DH + cc;
                *(__half2*)(cx + off) = __floats2half2_rn(cacc[mi][ni][half * 2],
                                                          cacc[mi][ni][half * 2 + 1]);
            }
        }
    }
}

// ================= launch =================
extern "C" void kernel_launch(void* const* d_in, const int* in_sizes, int n_in,
                              void* d_out, int out_size)
{
    const float* hidden = (const float*)d_in[0];
    const float* wts    = (const float*)d_in[1];
    const float* mk     = (const float*)d_in[2];
    const float* mv     = (const float*)d_in[3];
    const int*   idx    = (const int*)d_in[4];
    const float* pw     = (const float*)d_in[5];
    const float* qw     = (const float*)d_in[6];
    const float* ow     = (const float*)d_in[7];
    float* out = (float*)d_out;

    __half *xn, *qw16, *ow16, *cx;
    float *qbuf;
    cudaGetSymbolAddress((void**)&xn, g_xn);
    cudaGetSymbolAddress((void**)&qw16, g_qw16);
    cudaGetSymbolAddress((void**)&ow16, g_ow16);
    cudaGetSymbolAddress((void**)&cx, g_cx);
    cudaGetSymbolAddress((void**)&qbuf, g_q);

    cudaFuncSetAttribute(gemm1_kernel, cudaFuncAttributeMaxDynamicSharedMemorySize, GEMM_SMEM);
    cudaFuncSetAttribute(attn_fp16_kernel, cudaFuncAttributeMaxDynamicSharedMemorySize, ATTN_SMEM);

    rmsnorm_h_kernel<<<MROWS, 256>>>(hidden, pw, xn);
    cvt_h_kernel<<<(EDIM * EDIM / 4 + 255) / 256, 256>>>(qw, qw16, EDIM * EDIM / 4);
    cvt_h_kernel<<<(EDIM * EDIM / 4 + 255) / 256, 256>>>(ow, ow16, EDIM * EDIM / 4);

    gemm1_kernel<<<dim3(16, 32), 256, GEMM_SMEM>>>(xn, qw16, nullptr, qbuf);
    attn_fp16_kernel<<<NB * BQ * HKVN * 2, 256, ATTN_SMEM>>>(qbuf, mk, mv, idx, wts, cx);
    gemm1_kernel<<<dim3(16, 32), 256, GEMM_SMEM>>>(cx, ow16, hidden, out);
}